// round 3
// baseline (speedup 1.0000x reference)
#include <cuda_runtime.h>
#include <cuda_bf16.h>
#include <math.h>

#define NN 16384
#define MAXE 163840
#define MAXT (MAXE + NN)   // edges + self loops

// ---------------- scratch (device globals; no runtime alloc) ----------------
__device__ float g_h1[NN * 512];      // layer1 GEMM output
__device__ float g_h2in[NN * 512];    // gelu(layer1 out)  (input to GEMM2)
__device__ float g_h2[NN * 256];      // layer2 GEMM output
__device__ float g_adst1[NN * 4];
__device__ float g_asrc1[NN * 4];
__device__ float g_adst2[NN];
__device__ float g_asrc2[NN];
__device__ int   g_cnt[NN];
__device__ int   g_rowptr[NN + 1];
__device__ int   g_pos[NN];
__device__ int   g_csrsrc[MAXT];
__device__ float g_alpha[MAXT * 4];

// ---------------- CSR build ----------------
__global__ void zero_cnt_k() {
    int i = blockIdx.x * blockDim.x + threadIdx.x;
    if (i < NN) g_cnt[i] = 0;
}

__global__ void count_k(const int* __restrict__ dst, int E) {
    int i = blockIdx.x * blockDim.x + threadIdx.x;
    int tot = E + NN;
    if (i < tot) {
        int d = (i < E) ? dst[i] : (i - E);   // self loop for node (i-E)
        atomicAdd(&g_cnt[d], 1);
    }
}

// single block, 1024 threads, 16 elems each -> 16384
__global__ void scan_k() {
    __shared__ int sh[1024];
    int t = threadIdx.x;
    int base = t * 16;
    int local[16];
    int s = 0;
#pragma unroll
    for (int k = 0; k < 16; k++) { local[k] = s; s += g_cnt[base + k]; }
    sh[t] = s;
    __syncthreads();
    for (int off = 1; off < 1024; off <<= 1) {
        int v = (t >= off) ? sh[t - off] : 0;
        __syncthreads();
        sh[t] += v;
        __syncthreads();
    }
    int excl = sh[t] - s;
#pragma unroll
    for (int k = 0; k < 16; k++) {
        g_rowptr[base + k] = excl + local[k];
        g_pos[base + k]    = excl + local[k];
    }
    if (t == 1023) g_rowptr[NN] = sh[1023];
}

__global__ void scatter_k(const int* __restrict__ src, const int* __restrict__ dst, int E) {
    int i = blockIdx.x * blockDim.x + threadIdx.x;
    int tot = E + NN;
    if (i < tot) {
        int s, d;
        if (i < E) { s = src[i]; d = dst[i]; }
        else       { s = i - E;  d = i - E; }
        int p = atomicAdd(&g_pos[d], 1);
        g_csrsrc[p] = s;
    }
}

// ---------------- SGEMM: C[M,N] = A[M,K] @ B[K,N], all row-major ----------------
// LAYER==1: A = x (param), C = g_h1,   M=NN, N=512, K=256
// LAYER==2: A = g_h2in,    C = g_h2,   M=NN, N=256, K=512
template <int LAYER>
__global__ __launch_bounds__(256) void sgemm128_k(const float* __restrict__ Ain,
                                                  const float* __restrict__ B) {
    const int N = (LAYER == 1) ? 512 : 256;
    const int K = (LAYER == 1) ? 256 : 512;
    const float* A = (LAYER == 1) ? Ain : g_h2in;
    float* C = (LAYER == 1) ? g_h1 : g_h2;

    __shared__ float As[8][128];
    __shared__ float Bs[8][128];
    int col0 = blockIdx.x * 128;
    int row0 = blockIdx.y * 128;
    int t  = threadIdx.x;
    int tx = t & 15, ty = t >> 4;

    float acc[8][8];
#pragma unroll
    for (int i = 0; i < 8; i++)
#pragma unroll
        for (int j = 0; j < 8; j++) acc[i][j] = 0.f;

    int arow = t >> 1, acol = (t & 1) * 4;
    int brow = t >> 5, bcol = (t & 31) * 4;
    const float* Ap = A + (size_t)(row0 + arow) * K + acol;
    const float* Bp = B + (size_t)brow * N + col0 + bcol;

    for (int k0 = 0; k0 < K; k0 += 8) {
        float4 av = *(const float4*)(Ap + k0);
        float4 bv = *(const float4*)(Bp + (size_t)k0 * N);
        As[acol + 0][arow] = av.x;
        As[acol + 1][arow] = av.y;
        As[acol + 2][arow] = av.z;
        As[acol + 3][arow] = av.w;
        *(float4*)&Bs[brow][bcol] = bv;
        __syncthreads();
#pragma unroll
        for (int kk = 0; kk < 8; kk++) {
            float ra[8], rb[8];
#pragma unroll
            for (int i = 0; i < 8; i++) ra[i] = As[kk][ty * 8 + i];
#pragma unroll
            for (int j = 0; j < 8; j++) rb[j] = Bs[kk][tx * 8 + j];
#pragma unroll
            for (int i = 0; i < 8; i++)
#pragma unroll
                for (int j = 0; j < 8; j++) acc[i][j] = fmaf(ra[i], rb[j], acc[i][j]);
        }
        __syncthreads();
    }
#pragma unroll
    for (int i = 0; i < 8; i++) {
        float* Cp = C + (size_t)(row0 + ty * 8 + i) * N + col0 + tx * 8;
#pragma unroll
        for (int j = 0; j < 8; j += 4) {
            float4 v = make_float4(acc[i][j], acc[i][j + 1], acc[i][j + 2], acc[i][j + 3]);
            *(float4*)(Cp + j) = v;
        }
    }
}

// ---------------- per-node attention scalars ----------------
// adst[n,h] = dot(h[n, h*C : h*C+C], att[h, 0:C])
// asrc[n,h] = dot(h[n, h*C : h*C+C], att[h, C:2C])
template <int LAYER>
__global__ void node_att_k(const float* __restrict__ att) {
    const int H = (LAYER == 1) ? 4 : 1;
    const int C = (LAYER == 1) ? 128 : 256;
    const float* hfeat = (LAYER == 1) ? g_h1 : g_h2;
    float* adst = (LAYER == 1) ? g_adst1 : g_adst2;
    float* asrc = (LAYER == 1) ? g_asrc1 : g_asrc2;

    int warp = threadIdx.x >> 5, lane = threadIdx.x & 31;
    int n = blockIdx.x * 4 + warp;
    if (n >= NN) return;
#pragma unroll
    for (int h = 0; h < H; h++) {
        float sd = 0.f, ss = 0.f;
#pragma unroll
        for (int k = 0; k < C / 32; k++) {
            int c = lane + 32 * k;
            float v = hfeat[(size_t)n * H * C + h * C + c];
            sd += v * att[h * 2 * C + c];
            ss += v * att[h * 2 * C + C + c];
        }
#pragma unroll
        for (int off = 16; off > 0; off >>= 1) {
            sd += __shfl_xor_sync(0xffffffffu, sd, off);
            ss += __shfl_xor_sync(0xffffffffu, ss, off);
        }
        if (lane == 0) {
            adst[n * H + h] = sd;
            asrc[n * H + h] = ss;
        }
    }
}

__device__ __forceinline__ float sigmoidf_(float x) { return 1.f / (1.f + __expf(-x)); }

// ---------------- fused edge-attention + segment softmax + aggregation ----------------
// one CTA (128 threads, 4 warps) per destination node
// LAYER==1: hfeat=g_h1,  out=g_h2in (with GELU), H=4, C=128
// LAYER==2: hfeat=g_h2,  out=param (no GELU),    H=1, C=256
template <int LAYER>
__global__ __launch_bounds__(128) void attn_k(const float* __restrict__ bias,
                                              float* __restrict__ outp) {
    const int H = (LAYER == 1) ? 4 : 1;
    const int C = (LAYER == 1) ? 128 : 256;
    const bool GELU = (LAYER == 1);
    const int D = H * C;
    const int KC = C / 32;
    const float* hfeat = (LAYER == 1) ? g_h1 : g_h2;
    const float* adst  = (LAYER == 1) ? g_adst1 : g_adst2;
    const float* asrc  = (LAYER == 1) ? g_asrc1 : g_asrc2;
    float* out = (LAYER == 1) ? g_h2in : outp;

    int n = blockIdx.x;
    int t = threadIdx.x;
    int warp = t >> 5, lane = t & 31;

    __shared__ float hd[D];
    __shared__ float sh_acc[4][D];
    __shared__ float wred[4][H];
    __shared__ float sh_m[H];
    __shared__ float sh_s[H];

    for (int i = t; i < D; i += 128) hd[i] = hfeat[(size_t)n * D + i];
    __syncthreads();

    int r0 = g_rowptr[n], r1 = g_rowptr[n + 1];

    float ad[H];
#pragma unroll
    for (int h = 0; h < H; h++) ad[h] = adst[n * H + h];

    // ---- pass 1: logits -> alpha_pre, per-warp max ----
    float wmax[H];
#pragma unroll
    for (int h = 0; h < H; h++) wmax[h] = -1e30f;

    for (int p = r0 + warp; p < r1; p += 4) {
        int s = g_csrsrc[p];
        const float* hs = hfeat + (size_t)s * D;
        float dot[H];
#pragma unroll
        for (int h = 0; h < H; h++) {
            float d = 0.f;
#pragma unroll
            for (int k = 0; k < KC; k++) {
                int idx = h * C + lane + 32 * k;
                d = fmaf(hs[idx], hd[idx], d);
            }
            dot[h] = d;
        }
#pragma unroll
        for (int h = 0; h < H; h++)
#pragma unroll
            for (int off = 16; off > 0; off >>= 1)
                dot[h] += __shfl_xor_sync(0xffffffffu, dot[h], off);

#pragma unroll
        for (int h = 0; h < H; h++) {
            float al = (ad[h] + asrc[s * H + h]) * sigmoidf_(dot[h]);
            al = (al >= 0.f) ? al : 0.2f * al;     // leaky relu
            if (lane == 0) g_alpha[(size_t)p * H + h] = al;
            wmax[h] = fmaxf(wmax[h], al);
        }
    }
    if (lane == 0)
#pragma unroll
        for (int h = 0; h < H; h++) wred[warp][h] = wmax[h];
    __syncthreads();
    if (t < H) {
        float m = fmaxf(fmaxf(wred[0][t], wred[1][t]), fmaxf(wred[2][t], wred[3][t]));
        sh_m[t] = m;
    }
    __syncthreads();

    float m[H];
#pragma unroll
    for (int h = 0; h < H; h++) m[h] = sh_m[h];

    // ---- pass 2: exp, weighted accumulation ----
    float acc[H * KC > 0 ? H * KC : 1];
#pragma unroll
    for (int i = 0; i < H * KC; i++) acc[i] = 0.f;
    float wsum[H];
#pragma unroll
    for (int h = 0; h < H; h++) wsum[h] = 0.f;

    for (int p = r0 + warp; p < r1; p += 4) {
        int s = g_csrsrc[p];
        const float* hs = hfeat + (size_t)s * D;
#pragma unroll
        for (int h = 0; h < H; h++) {
            float ex = __expf(g_alpha[(size_t)p * H + h] - m[h]);
            wsum[h] += ex;
#pragma unroll
            for (int k = 0; k < KC; k++) {
                int idx = h * C + lane + 32 * k;
                acc[h * KC + k] = fmaf(ex, hs[idx], acc[h * KC + k]);
            }
        }
    }
    if (lane == 0)
#pragma unroll
        for (int h = 0; h < H; h++) wred[warp][h] = wsum[h];

    // stage per-warp partials
#pragma unroll
    for (int h = 0; h < H; h++)
#pragma unroll
        for (int k = 0; k < KC; k++)
            sh_acc[warp][h * C + lane + 32 * k] = acc[h * KC + k];
    __syncthreads();

    if (t < H) sh_s[t] = wred[0][t] + wred[1][t] + wred[2][t] + wred[3][t] + 1e-16f;
    __syncthreads();

    for (int i = t; i < D; i += 128) {
        float v = sh_acc[0][i] + sh_acc[1][i] + sh_acc[2][i] + sh_acc[3][i];
        int h = i / C;
        v = v / sh_s[h];
        v += bias[i];
        if (GELU) v = 0.5f * v * (1.f + erff(v * 0.70710678118654752f));
        out[(size_t)n * D + i] = v;
    }
}

// ---------------- launch ----------------
extern "C" void kernel_launch(void* const* d_in, const int* in_sizes, int n_in,
                              void* d_out, int out_size) {
    const float* x    = (const float*)d_in[0];
    const int*   ei   = (const int*)d_in[1];
    const float* W1   = (const float*)d_in[2];
    const float* att1 = (const float*)d_in[3];
    const float* b1   = (const float*)d_in[4];
    const float* W2   = (const float*)d_in[5];
    const float* att2 = (const float*)d_in[6];
    const float* b2   = (const float*)d_in[7];
    float* outp = (float*)d_out;

    int E = in_sizes[1] / 2;
    const int* src = ei;
    const int* dst = ei + E;
    int tot = E + NN;

    // CSR (shared by both layers)
    zero_cnt_k<<<NN / 256, 256>>>();
    count_k<<<(tot + 255) / 256, 256>>>(dst, E);
    scan_k<<<1, 1024>>>();
    scatter_k<<<(tot + 255) / 256, 256>>>(src, dst, E);

    // layer 1
    sgemm128_k<1><<<dim3(512 / 128, NN / 128), 256>>>(x, W1);
    node_att_k<1><<<NN / 4, 128>>>(att1);
    attn_k<1><<<NN, 128>>>(b1, nullptr);

    // layer 2
    sgemm128_k<2><<<dim3(256 / 128, NN / 128), 256>>>(nullptr, W2);
    node_att_k<2><<<NN / 4, 128>>>(att2);
    attn_k<2><<<NN, 128>>>(b2, outp);
}